// round 4
// baseline (speedup 1.0000x reference)
#include <cuda_runtime.h>
#include <cstdint>

#define Bq 32
#define Tq 1024
#define Iq 64
#define Hq 512
#define Aq 16

#define OUT_N  (Bq*Tq*Aq)          // 524288
#define HN_N   (Bq*Hq)             // 16384
#define HN_OFF OUT_N
#define RNN_OFF (OUT_N + HN_N)     // 540672

#define CLU 8                      // CTAs per cluster
#define NCL 16                     // clusters (16*8 = 128 CTAs)
#define NB  2                      // batches per cluster
#define TXB 4096                   // bytes per mbarrier phase: 8 CTAs * 128 vals * 4B
#define HROW 528                   // skewed h row stride (floats), HSK(511)=525
#define HBUF (NB*HROW)             // 1056 floats per buffer

typedef unsigned long long u64;

// ---- scratch (static device globals: allocation-free) ----
__device__ float g_xp[Tq*Bq*Hq];               // x_proj [t][b][j]   (64 MB)
__device__ float g_hidden[(size_t)Bq*Tq*Hq];   // fc1 output (64 MB)

// ================= helpers =================
__device__ __forceinline__ uint32_t smem_u32(const void* p) {
    uint32_t a;
    asm("{ .reg .u64 t; cvta.to.shared.u64 t, %1; cvt.u32.u64 %0, t; }" : "=r"(a) : "l"(p));
    return a;
}
__device__ __forceinline__ uint32_t mapa_u32(uint32_t laddr, uint32_t rank) {
    uint32_t r;
    asm("mapa.shared::cluster.u32 %0, %1, %2;" : "=r"(r) : "r"(laddr), "r"(rank));
    return r;
}
__device__ __forceinline__ void st_async_f32(uint32_t raddr, float v, uint32_t rmbar) {
    asm volatile("st.async.shared::cluster.mbarrier::complete_tx::bytes.b32 [%0], %1, [%2];"
                 :: "r"(raddr), "f"(v), "r"(rmbar) : "memory");
}
__device__ __forceinline__ void mbar_init(uint32_t mbar, uint32_t cnt) {
    asm volatile("mbarrier.init.shared.b64 [%0], %1;" :: "r"(mbar), "r"(cnt) : "memory");
}
__device__ __forceinline__ void mbar_arrive_expect_tx(uint32_t mbar, uint32_t tx) {
    asm volatile("mbarrier.arrive.expect_tx.shared.b64 _, [%0], %1;" :: "r"(mbar), "r"(tx) : "memory");
}
__device__ __forceinline__ void mbar_wait_parity(uint32_t mbar, uint32_t parity) {
    asm volatile(
        "{\n\t"
        ".reg .pred P1;\n\t"
        "WAIT_LOOP_%=:\n\t"
        "mbarrier.try_wait.parity.acquire.cluster.shared::cta.b64 P1, [%0], %1, 0x989680;\n\t"
        "@P1 bra.uni WAIT_DONE_%=;\n\t"
        "bra.uni WAIT_LOOP_%=;\n\t"
        "WAIT_DONE_%=:\n\t"
        "}" :: "r"(mbar), "r"(parity) : "memory");
}
// packed f32x2 on 64-bit carriers: NO per-call mov repacking
__device__ __forceinline__ u64 ffma2(u64 a, u64 b, u64 c) {
    u64 d;
    asm("fma.rn.f32x2 %0, %1, %2, %3;" : "=l"(d) : "l"(a), "l"(b), "l"(c));
    return d;
}
__device__ __forceinline__ u64 packf2(float x, float y) {
    u64 r; asm("mov.b64 %0, {%1,%2};" : "=l"(r) : "f"(x), "f"(y)); return r;
}
__device__ __forceinline__ float2 unpackf2(u64 v) {
    float2 f; asm("mov.b64 {%0,%1}, %2;" : "=f"(f.x), "=f"(f.y) : "l"(v)); return f;
}
__device__ __forceinline__ float hsum2(u64 v) { float2 f = unpackf2(v); return f.x + f.y; }

// ---------------- x_proj: xp[t][b][j] = sum_i inp[b][t][i] * w_ih[i][j] ----------------
__global__ void __launch_bounds__(512) xp_kernel(const float* __restrict__ inp,
                                                 const float* __restrict__ w_ih) {
    const int b   = blockIdx.x;   // 32
    const int tc  = blockIdx.y;   // 32 chunks of 32 timesteps
    const int tid = threadIdx.x;  // 512 (j)
    __shared__ __align__(16) float s_in[32*64];
    const float* src = inp + (size_t)b*Tq*Iq + (size_t)tc*32*Iq;
    ((float4*)s_in)[tid] = ((const float4*)src)[tid];
    __syncthreads();

    u64 acc[32];
    #pragma unroll
    for (int tt = 0; tt < 32; tt++) acc[tt] = 0ull;

    #pragma unroll 4
    for (int ip = 0; ip < 32; ip++) {           // k-pair over i
        u64 wpk = packf2(w_ih[(2*ip)*Hq + tid], w_ih[(2*ip + 1)*Hq + tid]);
        #pragma unroll
        for (int tt = 0; tt < 32; tt++)
            acc[tt] = ffma2(*(const u64*)&s_in[tt*64 + 2*ip], wpk, acc[tt]);
    }
    #pragma unroll
    for (int tt = 0; tt < 32; tt++)
        g_xp[(size_t)(tc*32 + tt)*(Bq*Hq) + b*Hq + tid] = hsum2(acc[tt]);
}

// ---------------- RNN scan: 16 clusters of 8 CTAs, no in-loop __syncthreads ----------------
// lane = s*4 + q (s = k-segment 0..7, q = col-quad). warp w owns cols [w*8, w*8+8) of the
// CTA's 64-col slice, for both batches. Weights in regs (64 u64). h skewed in SMEM.
// HSK(k) = k + (k>>6)*2 -> segment s starts at s*66 floats (conflict-free LDS.64).
__global__ void __launch_bounds__(256, 1) __cluster_dims__(CLU, 1, 1)
rnn_kernel(const float* __restrict__ hn, const float* __restrict__ w_hh,
           float* __restrict__ outbuf) {
    __shared__ __align__(16) float h_s[2][HBUF];           // skewed [buf][b*528 + HSK(k)]
    __shared__ __align__(8)  unsigned long long mbar_s[2];

    const int tid = threadIdx.x;
    uint32_t rank;
    asm("mov.u32 %0, %%cluster_ctarank;" : "=r"(rank));
    const int cid = blockIdx.x >> 3;
    const int j0  = (int)rank * 64;
    const int w   = tid >> 5;
    const int l   = tid & 31;
    const int s   = l >> 2;           // k-segment (within warp)
    const int q   = l & 3;            // col quad
    const int c0  = w*8 + q*2;        // local col pair base
    const int kb  = s * 64;

    // ---- stationary weights: Wc0[m]=(w[kb+2m][j0+c0], w[kb+2m+1][j0+c0]), Wc1 for c0+1 ----
    u64 Wc0[32], Wc1[32];
    {
        const float* wbase = w_hh + (size_t)kb*Hq + j0 + c0;
        #pragma unroll
        for (int m = 0; m < 32; m++) {
            const float* wp = wbase + (size_t)(2*m)*Hq;
            Wc0[m] = packf2(wp[0], wp[Hq]);
            Wc1[m] = packf2(wp[1], wp[Hq + 1]);
        }
    }
    // ---- h0 into buffer 0 (skewed) ----
    for (int e = tid; e < NB*Hq; e += 256) {
        int b = e >> 9, k = e & 511;
        h_s[0][b*HROW + k + ((k >> 6) << 1)] = hn[(size_t)(cid*NB + b)*Hq + k];
    }
    const uint32_t mbar0 = smem_u32(&mbar_s[0]);
    if (tid == 0) { mbar_init(mbar0, 1); mbar_init(mbar0 + 8, 1); }
    __syncthreads();
    asm volatile("barrier.cluster.arrive.aligned;" ::: "memory");
    asm volatile("barrier.cluster.wait.aligned;"   ::: "memory");

    // ---- per-lane output identity (lanes s<4 push) ----
    const int out_b = (s >> 1) & 1;
    const int jglob = j0 + c0 + (s & 1);
    const int jskew = jglob + ((jglob >> 6) << 1);
    // remote addresses for buffer 0 (buffer 1 = +HBUF*4 bytes; mbar 1 = +8)
    const uint32_t loff0 = smem_u32(&h_s[0][out_b*HROW + jskew]);
    uint32_t da[CLU], ma[CLU];
    #pragma unroll
    for (int r = 0; r < CLU; r++) {
        da[r] = mapa_u32(loff0, (uint32_t)r);
        ma[r] = mapa_u32(mbar0, (uint32_t)r);
    }
    const float* xp_ptr  = g_xp + (size_t)(cid*NB + out_b)*Hq + jglob;
    float*       rnn_ptr = outbuf + RNN_OFF + (size_t)(cid*NB + out_b)*Tq*Hq + jglob;

    for (int t = 0; t < Tq; t++) {
        const int cur = t & 1, nxt = cur ^ 1;
        if (t > 0) mbar_wait_parity(mbar0 + 8u*cur, (uint32_t)(((t - 1) >> 1) & 1));
        if (tid == 0 && t < Tq - 1) mbar_arrive_expect_tx(mbar0 + 8u*nxt, TXB);

        float xpv = 0.f;
        if (s < 4) xpv = __ldcg(xp_ptr + (size_t)t*(Bq*Hq));

        // ---- GEMV: 2 batches x 2 cols over 64 k, pure packed FFMA2 ----
        const float* hb = &h_s[cur][s*66];
        u64 a00 = 0ull, a01 = 0ull, a10 = 0ull, a11 = 0ull;
        #pragma unroll
        for (int m = 0; m < 32; m++) {
            u64 h0 = *(const u64*)&hb[2*m];
            u64 h1 = *(const u64*)&hb[HROW + 2*m];
            a00 = ffma2(h0, Wc0[m], a00);
            a01 = ffma2(h0, Wc1[m], a01);
            a10 = ffma2(h1, Wc0[m], a10);
            a11 = ffma2(h1, Wc1[m], a11);
        }
        // ---- warp shuffle reduce across the 8 segments (lane bits 2..4) ----
        float f00 = hsum2(a00), f01 = hsum2(a01), f10 = hsum2(a10), f11 = hsum2(a11);
        #pragma unroll
        for (int off = 4; off <= 16; off <<= 1) {
            f00 += __shfl_xor_sync(0xffffffffu, f00, off);
            f01 += __shfl_xor_sync(0xffffffffu, f01, off);
            f10 += __shfl_xor_sync(0xffffffffu, f10, off);
            f11 += __shfl_xor_sync(0xffffffffu, f11, off);
        }

        if (s < 4) {
            float v = (s & 2) ? ((s & 1) ? f11 : f10) : ((s & 1) ? f01 : f00);
            v += xpv;
            float hv = 1.f / (1.f + __expf(-v));
            rnn_ptr[(size_t)t*Hq] = hv;
            if (t == Tq - 1) {
                outbuf[HN_OFF + (size_t)(cid*NB + out_b)*Hq + jglob] = hv;
            } else {
                const uint32_t doff = (uint32_t)(nxt * (HBUF*4));
                const uint32_t moff = (uint32_t)(nxt * 8);
                #pragma unroll
                for (int r = 0; r < CLU; r++)
                    st_async_f32(da[r] + doff, hv, ma[r] + moff);
            }
        }
    }
}

// ---------------- fc1: hidden = relu(rnn_out @ fc1_w + b1), 64x64 tiles, u64 FFMA2 ----------------
__global__ void __launch_bounds__(256) fc1_kernel(const float* __restrict__ A,   // [32768, 512]
                                                  const float* __restrict__ W,   // [512, 512]
                                                  const float* __restrict__ bias) {
    __shared__ __align__(16) float  As[64*32];     // [r][k] 8KB
    __shared__ __align__(16) float2 Ws2[16*64];    // [kk][c] = (W[2kk][c], W[2kk+1][c]) 8KB
    const int tid = threadIdx.x;      // 256
    const int bx = blockIdx.x;        // 8 col tiles
    const int by = blockIdx.y;        // 512 row tiles
    const int tx = tid & 15, ty = tid >> 4;
    const int row0 = by*64, col0 = bx*64;

    u64 acc[4][4];
    #pragma unroll
    for (int i = 0; i < 4; i++)
        #pragma unroll
        for (int j = 0; j < 4; j++) acc[i][j] = 0ull;

    for (int kt = 0; kt < Hq; kt += 32) {
        {
            int r = tid >> 3, kq = (tid & 7) << 2;
            *(float4*)&As[r*32 + kq]      = *(const float4*)&A[(size_t)(row0 + r)*Hq + kt + kq];
            *(float4*)&As[(r+32)*32 + kq] = *(const float4*)&A[(size_t)(row0 + r + 32)*Hq + kt + kq];
            #pragma unroll
            for (int i = 0; i < 4; i++) {
                int u = tid + i*256;
                int kk = u >> 6, c = u & 63;
                const float* wp = &W[(size_t)(kt + 2*kk)*Hq + col0 + c];
                Ws2[kk*64 + c] = make_float2(wp[0], wp[Hq]);
            }
        }
        __syncthreads();
        #pragma unroll
        for (int kk = 0; kk < 16; kk++) {
            ulonglong2 wa = *(const ulonglong2*)&Ws2[kk*64 + tx*4];
            ulonglong2 wb = *(const ulonglong2*)&Ws2[kk*64 + tx*4 + 2];
            #pragma unroll
            for (int r4 = 0; r4 < 4; r4++) {
                u64 a2 = *(const u64*)&As[(ty*4 + r4)*32 + 2*kk];
                acc[r4][0] = ffma2(a2, wa.x, acc[r4][0]);
                acc[r4][1] = ffma2(a2, wa.y, acc[r4][1]);
                acc[r4][2] = ffma2(a2, wb.x, acc[r4][2]);
                acc[r4][3] = ffma2(a2, wb.y, acc[r4][3]);
            }
        }
        __syncthreads();
    }

    float4 bv = *(const float4*)&bias[col0 + tx*4];
    #pragma unroll
    for (int i = 0; i < 4; i++) {
        float4 o;
        o.x = fmaxf(hsum2(acc[i][0]) + bv.x, 0.f);
        o.y = fmaxf(hsum2(acc[i][1]) + bv.y, 0.f);
        o.z = fmaxf(hsum2(acc[i][2]) + bv.z, 0.f);
        o.w = fmaxf(hsum2(acc[i][3]) + bv.w, 0.f);
        *(float4*)&g_hidden[(size_t)(row0 + ty*4 + i)*Hq + col0 + tx*4] = o;
    }
}

// ---------------- fc2: out = sigmoid(hidden @ fc2_w + b2), u64 FFMA2, 4 chains ----------------
__global__ void __launch_bounds__(256) fc2_kernel(const float* __restrict__ w2,   // [512, 16]
                                                  const float* __restrict__ b2,
                                                  float* __restrict__ out) {
    __shared__ __align__(16) float2 w2s[256*16];   // [kk][a] = (w2[2kk][a], w2[2kk+1][a]) 32KB
    const int tid = threadIdx.x;   // 256
    for (int e = tid; e < 256*16; e += 256) {
        int kk = e >> 4, a = e & 15;
        w2s[e] = make_float2(w2[(2*kk)*Aq + a], w2[(2*kk+1)*Aq + a]);
    }
    __syncthreads();

    const int r = tid >> 4;
    const int a = tid & 15;
    const size_t row = (size_t)blockIdx.x * 16 + r;
    const ulonglong2* hp = (const ulonglong2*)&g_hidden[row*Hq];

    u64 acc0 = 0ull, acc1 = 0ull, acc2 = 0ull, acc3 = 0ull;
    #pragma unroll 4
    for (int p = 0; p < 256; p += 4) {            // k-pairs
        ulonglong2 ha = hp[(p >> 1)];
        ulonglong2 hb = hp[(p >> 1) + 1];
        acc0 = ffma2(ha.x, *(const u64*)&w2s[(p+0)*16 + a], acc0);
        acc1 = ffma2(ha.y, *(const u64*)&w2s[(p+1)*16 + a], acc1);
        acc2 = ffma2(hb.x, *(const u64*)&w2s[(p+2)*16 + a], acc2);
        acc3 = ffma2(hb.y, *(const u64*)&w2s[(p+3)*16 + a], acc3);
    }
    float v = (hsum2(acc0) + hsum2(acc1)) + (hsum2(acc2) + hsum2(acc3)) + b2[a];
    out[row*Aq + a] = 1.f / (1.f + __expf(-v));
}

extern "C" void kernel_launch(void* const* d_in, const int* in_sizes, int n_in,
                              void* d_out, int out_size) {
    const float* inp  = (const float*)d_in[0];
    const float* hn   = (const float*)d_in[1];
    const float* w_hh = (const float*)d_in[2];
    const float* w_ih = (const float*)d_in[3];
    const float* fc1w = (const float*)d_in[4];
    const float* fc1b = (const float*)d_in[5];
    const float* fc2w = (const float*)d_in[6];
    const float* fc2b = (const float*)d_in[7];
    float* out = (float*)d_out;

    xp_kernel<<<dim3(32, 32), 512>>>(inp, w_ih);
    rnn_kernel<<<NCL*CLU, 256>>>(hn, w_hh, out);
    fc1_kernel<<<dim3(8, 512), 256>>>(out + RNN_OFF, fc1w, fc1b);
    fc2_kernel<<<(Bq*Tq)/16, 256>>>(fc2w, fc2b, out);
}